// round 7
// baseline (speedup 1.0000x reference)
#include <cuda_runtime.h>

// ---------------------------------------------------------------------------
// SSIM loss, fully fused:  out = 1 - mean(ssim_map(img1, img2))
// (32,3,512,512) fp32, 11x11 Gaussian sigma=1.5, SAME zero padding.
//
// Blur 4 maps {x, y, x*x+y*y, x*y}. Warp-autonomous 64-col strips; per row:
// stage maps into warp-private double-buffered smem (1 __syncwarp/row),
// 11-tap horizontal blur (FFMA-imm), pack (colA,colB) into a u64 ring of 11
// h-blurred rows, 11-tap vertical blur as packed fma.rn.f32x2 (FFMA2, one
// issue slot per 2 FMAs) with statically rotated ring indices (row_step<JJ>),
// SSIM epilogue, accumulate. Branch-free borders: clamped incremented row
// pointers + {0,1} masks folded into staging. Final reduction fused via
// last-block atomic counter (deterministic fixed-order double sum,
// self-resetting for graph replay).
// ---------------------------------------------------------------------------

namespace {
constexpr int HW      = 512;
constexpr int NT      = 128;                 // 4 warps per CTA
constexpr int RC      = 256;                 // output rows per CTA
constexpr int WSTRIDE = 80;                  // smem floats per map row (>=74)
constexpr int NCTAS   = 2 * 2 * 96;          // strips x chunks x planes = 384
constexpr int NPART   = NCTAS * 4;           // one partial per warp = 1536
constexpr float C1    = 0.01f * 0.01f;
constexpr float C2    = 0.03f * 0.03f;

// Normalized 1D Gaussian, window 11, sigma 1.5 (symmetric)
__device__ constexpr float WG[11] = {
    0.00102838f, 0.00759876f, 0.03600078f, 0.10936069f, 0.21300554f,
    0.26601173f,
    0.21300554f, 0.10936069f, 0.03600078f, 0.00759876f, 0.00102838f
};
}  // namespace

__device__ float g_partials[NPART];
__device__ int   g_count = 0;

// Packed fp32x2 helpers (sm_103a FFMA2 path — not emitted from plain C++)
#define FMA2(acc, val, w) \
    asm("fma.rn.f32x2 %0, %1, %2, %0;" : "+l"(acc) : "l"(val), "l"(w))
#define PK(p, lo, hi) \
    asm("mov.b64 %0, {%1, %2};" : "=l"(p) : "f"(lo), "f"(hi))
#define UNPK(lo, hi, p) \
    asm("mov.b64 {%0, %1}, %2;" : "=f"(lo), "=f"(hi) : "l"(p))

// One row of the pipeline. JJ = i mod 11 (compile-time ring phase).
template <int JJ>
__device__ __forceinline__ void row_step(
    int lane, int& rr,
    const char*& r1, const char*& r2,
    int off0, int off1, int off2,
    float cm0, float cm1, float cm2,
    float* __restrict__ sw, int sbsel,
    unsigned long long (&ring)[11][4],
    const unsigned long long (&wpk)[6],
    float (&pa)[6], float& arm,
    float& lsum, bool emit)
{
    // ---- stage row rr (held in pa): maps {x, y, x*x+y*y, x*y} ----
    float* sbuf = sw + sbsel;
    {
        float m0 = cm0 * arm, m1 = cm1 * arm, m2 = cm2 * arm;
        float xm = pa[0] * m0, ym = pa[1] * m0;
        int p = lane;
        sbuf[0 * WSTRIDE + p] = xm;
        sbuf[1 * WSTRIDE + p] = ym;
        sbuf[2 * WSTRIDE + p] = fmaf(xm, xm, ym * ym);
        sbuf[3 * WSTRIDE + p] = xm * ym;
        xm = pa[2] * m1; ym = pa[3] * m1; p = lane + 32;
        sbuf[0 * WSTRIDE + p] = xm;
        sbuf[1 * WSTRIDE + p] = ym;
        sbuf[2 * WSTRIDE + p] = fmaf(xm, xm, ym * ym);
        sbuf[3 * WSTRIDE + p] = xm * ym;
        if (lane < 10) {
            xm = pa[4] * m2; ym = pa[5] * m2; p = lane + 64;
            sbuf[0 * WSTRIDE + p] = xm;
            sbuf[1 * WSTRIDE + p] = ym;
            sbuf[2 * WSTRIDE + p] = fmaf(xm, xm, ym * ym);
            sbuf[3 * WSTRIDE + p] = xm * ym;
        }
    }

    // ---- prefetch next raw row (rr+1) back into pa (hidden by blur) ----
    {
        int nr = rr + 1;
        if ((unsigned)(nr - 1) < 511u) { r1 += 2048; r2 += 2048; }
        arm = ((unsigned)nr < 512u) ? 1.f : 0.f;
        rr = nr;
        pa[0] = *(const float*)(r1 + off0);
        pa[1] = *(const float*)(r2 + off0);
        pa[2] = *(const float*)(r1 + off1);
        pa[3] = *(const float*)(r2 + off1);
        if (lane < 10) {
            pa[4] = *(const float*)(r1 + off2);
            pa[5] = *(const float*)(r2 + off2);
        }
    }
    __syncwarp();

    // ---- horizontal 11-tap blur (FFMA-imm) -> packed ring slot JJ ----
#pragma unroll
    for (int m = 0; m < 4; ++m) {
        const float* rp = sbuf + m * WSTRIDE + 2 * lane;
        float v[12];
#pragma unroll
        for (int k = 0; k < 6; ++k) {
            float2 q = *(const float2*)(rp + 2 * k);  // 8B aligned
            v[2 * k]     = q.x;
            v[2 * k + 1] = q.y;
        }
        float A = 0.f, B = 0.f;
#pragma unroll
        for (int k = 0; k < 11; ++k) {
            A = fmaf(WG[k], v[k],     A);
            B = fmaf(WG[k], v[k + 1], B);
        }
        PK(ring[JJ][m], A, B);
    }

    // ---- vertical 11-tap blur: packed FFMA2 + SSIM + accumulate ----
    if (emit) {
        unsigned long long acc[4] = {0ull, 0ull, 0ull, 0ull};
#pragma unroll
        for (int m = 0; m < 11; ++m) {
            const int widx = 10 - ((JJ - m + 11) % 11);      // compile-time
            const int wi   = widx <= 5 ? widx : 10 - widx;   // symmetric
#pragma unroll
            for (int q = 0; q < 4; ++q)
                FMA2(acc[q], ring[m][q], wpk[wi]);
        }
        float s0[4], s1[4];
#pragma unroll
        for (int q = 0; q < 4; ++q) UNPK(s0[q], s1[q], acc[q]);
        {
            float mu1 = s0[0], mu2 = s0[1], bss = s0[2], bxy = s0[3];
            float m12 = mu1 * mu2;
            float msq = fmaf(mu1, mu1, mu2 * mu2);
            float num = fmaf(2.f, m12, C1) * fmaf(2.f, bxy - m12, C2);
            float den = (msq + C1) * (bss - msq + C2);
            lsum += __fdividef(num, den);
        }
        {
            float mu1 = s1[0], mu2 = s1[1], bss = s1[2], bxy = s1[3];
            float m12 = mu1 * mu2;
            float msq = fmaf(mu1, mu1, mu2 * mu2);
            float num = fmaf(2.f, m12, C1) * fmaf(2.f, bxy - m12, C2);
            float den = (msq + C1) * (bss - msq + C2);
            lsum += __fdividef(num, den);
        }
    }
}

__global__ void __launch_bounds__(NT, 3)
ssim_kernel(const float* __restrict__ img1, const float* __restrict__ img2,
            float* __restrict__ out)
{
    __shared__ __align__(16) float sb[4][2 * 4 * WSTRIDE];  // per-warp staging
    __shared__ double sdbl[NT];
    __shared__ int    s_last;

    const int t     = threadIdx.x;
    const int w     = t >> 5;
    const int lane  = t & 31;
    const int strip = blockIdx.x;   // 0..1
    const int chunk = blockIdx.y;   // 0..1
    const int plane = blockIdx.z;   // 0..95

    const int gy0  = chunk * RC;
    const int col0 = strip * 256 + w * 64 - 5;  // global col of staging pos 0

    // Per-slot clamped byte offsets + validity masks (computed once)
    int   off0, off1, off2;
    float cm0, cm1, cm2;
    {
        int c;
        c = col0 + lane;
        cm0  = (c >= 0 && c < 512) ? 1.f : 0.f;
        off0 = (c < 0 ? 0 : (c > 511 ? 511 : c)) * 4;
        c = col0 + lane + 32;
        cm1  = (c >= 0 && c < 512) ? 1.f : 0.f;
        off1 = (c < 0 ? 0 : (c > 511 ? 511 : c)) * 4;
        c = col0 + lane + 64;
        cm2  = (c >= 0 && c < 512) ? 1.f : 0.f;
        off2 = (c < 0 ? 0 : (c > 511 ? 511 : c)) * 4;
    }

    // Packed (w, w) weights for FFMA2 (6 unique, symmetric window)
    unsigned long long wpk[6];
#pragma unroll
    for (int k = 0; k < 6; ++k)
        asm("mov.b64 %0, {%1, %1};" : "=l"(wpk[k]) : "f"(WG[k]));

    float* sw_ = &sb[w][0];
    unsigned long long ring[11][4];
    float pa[6];
    float arm;
    float lsum = 0.f;

    // Initial prefetch: raw row gy0-5 into pa; row pointers track clamp(rr)
    int rr = gy0 - 5;
    const char* r1;
    const char* r2;
    {
        int rcl = rr < 0 ? 0 : rr;  // never > 511 here
        arm = (rr == rcl) ? 1.f : 0.f;
        r1 = (const char*)(img1 + (size_t)plane * HW * HW) + rcl * 2048;
        r2 = (const char*)(img2 + (size_t)plane * HW * HW) + rcl * 2048;
        pa[0] = *(const float*)(r1 + off0);
        pa[1] = *(const float*)(r2 + off0);
        pa[2] = *(const float*)(r1 + off1);
        pa[3] = *(const float*)(r2 + off1);
        if (lane < 10) {
            pa[4] = *(const float*)(r1 + off2);
            pa[5] = *(const float*)(r2 + off2);
        } else {
            pa[4] = 0.f; pa[5] = 0.f;
        }
    }

#define RS(J, SB, EMIT) row_step<J>(lane, rr, r1, r2, off0, off1, off2, \
                                    cm0, cm1, cm2, sw_, (SB), ring, wpk, \
                                    pa, arm, lsum, (EMIT))

    // Warmup: i = 0..9 (fill ring; no emission).  Buffer selector = (i&1)*320.
    RS(0, 0, false);   RS(1, 320, false); RS(2, 0, false);   RS(3, 320, false);
    RS(4, 0, false);   RS(5, 320, false); RS(6, 0, false);   RS(7, 320, false);
    RS(8, 0, false);   RS(9, 320, false);

    // Steady state: i = 10..263 -> 254 steps... handled as 23 blocks of 11
    // starting at i=10 (phase 10,0,1,...,9), then 3 tail steps (i=263..265).
    // i parity: block starts at even i=10; 11 odd-length blocks flip parity.
    for (int ib = 0; ib < 253; ib += 11) {
        // i = ib+10 .. ib+20 ; buffer parity of (ib+10): ib/11 even -> even
        if (((ib / 11) & 1) == 0) {
            RS(10, 0, true);  RS(0, 320, true); RS(1, 0, true);
            RS(2, 320, true); RS(3, 0, true);   RS(4, 320, true);
            RS(5, 0, true);   RS(6, 320, true); RS(7, 0, true);
            RS(8, 320, true); RS(9, 0, true);
        } else {
            RS(10, 320, true); RS(0, 0, true);  RS(1, 320, true);
            RS(2, 0, true);    RS(3, 320, true);RS(4, 0, true);
            RS(5, 320, true);  RS(6, 0, true);  RS(7, 320, true);
            RS(8, 0, true);    RS(9, 320, true);
        }
    }
    // Tail: i = 263, 264, 265  (263 is odd -> buffer 320)
    RS(10, 320, true);  // i=263, phase (263%11)=10
    RS(0, 0, true);     // i=264
    RS(1, 320, true);   // i=265
#undef RS

    // ---- deterministic warp reduction -> per-warp global partial ----
#pragma unroll
    for (int o = 16; o > 0; o >>= 1)
        lsum += __shfl_down_sync(0xffffffffu, lsum, o);
    if (lane == 0)
        g_partials[(((plane * 2) + chunk) * 2 + strip) * 4 + w] = lsum;
    __syncthreads();

    // ---- last-block finalize (fused; deterministic; self-resetting) ----
    if (t == 0) {
        __threadfence();
        s_last = (atomicAdd(&g_count, 1) == NCTAS - 1) ? 1 : 0;
    }
    __syncthreads();
    if (s_last) {
        __threadfence();
        double acc = 0.0;
#pragma unroll
        for (int k = 0; k < NPART / NT; ++k)
            acc += (double)g_partials[t * (NPART / NT) + k];
        sdbl[t] = acc;
        __syncthreads();
        for (int o = 64; o > 0; o >>= 1) {
            if (t < o) sdbl[t] += sdbl[t + o];
            __syncthreads();
        }
        if (t == 0) {
            out[0] = (float)(1.0 - sdbl[0] / 25165824.0);  // 32*3*512*512
            g_count = 0;  // reset for next graph replay
        }
    }
}

extern "C" void kernel_launch(void* const* d_in, const int* in_sizes, int n_in,
                              void* d_out, int out_size) {
    (void)in_sizes; (void)n_in; (void)out_size;
    const float* img1 = (const float*)d_in[0];
    const float* img2 = (const float*)d_in[1];
    dim3 grid(2, 2, 96);  // strips x row-chunks x (N*C) planes
    ssim_kernel<<<grid, NT>>>(img1, img2, (float*)d_out);
}